// round 2
// baseline (speedup 1.0000x reference)
#include <cuda_runtime.h>

#define N 1024
#define H 96
#define E 16384
#define NB 2      // nodes per block in GRU kernel
#define PW 8      // warps per block in pair kernel

// ---------------- scratch (device globals; no allocation allowed) ----------
__device__ float g_bufA[N*H];
__device__ float g_bufB[N*H];
__device__ float g_m[N*H];
__device__ float g_s[N*H];
__device__ float g_cnt[N];
__device__ float g_hi[N*H];
__device__ float g_hjb[N*H];
__device__ int   g_src[E];
__device__ int   g_tgt[E];
__device__ float g_WihT[96*288];
__device__ float g_WhhT[96*288];
__device__ float g_WaiT[96*96];
__device__ float g_WajT[96*96];
__device__ float g_Wo1T[96*96];
__device__ float g_Wo2T[96*96];

__device__ __forceinline__ float sigf(float v){
    return __fdividef(1.0f, 1.0f + __expf(-v));
}
__device__ __forceinline__ float leaky(float v){
    return (v >= 0.0f) ? v : 0.01f * v;
}

// ---------------- decode edge_index robustly (int64 vs int32 storage) ------
// If stored as little-endian int64 with values < 2^31, every odd int32 word is
// the (zero) high half. If stored as int32, odd words are genuine edge values
// (random in [0,1024), so 16 consecutive zeros is impossible in practice).
__global__ void k_decode(const int* __restrict__ ei32){
    int e = blockIdx.x * blockDim.x + threadIdx.x;
    if (e >= E) return;
    int odd_or = 0;
    #pragma unroll
    for (int q = 0; q < 16; q++) odd_or |= ei32[2*q + 1];
    int s, t;
    if (odd_or == 0){            // int64 layout
        s = ei32[2*e];
        t = ei32[2*(E + e)];
    } else {                     // int32 layout
        s = ei32[e];
        t = ei32[E + e];
    }
    // validate: guarantees no wild atomics downstream
    if ((unsigned)s >= N) s = -1;
    if ((unsigned)t >= N) t = -1;
    g_src[e] = s;
    g_tgt[e] = t;
}

// ---------------- prep: transpose weights for coalesced dot-product reads --
__global__ void k_prep(const float* __restrict__ Wih, const float* __restrict__ Whh,
                       const float* __restrict__ Wa1,
                       const float* __restrict__ Wo1, const float* __restrict__ Wo2){
    int t = blockIdx.x * blockDim.x + threadIdx.x;
    if (t < 288*96){
        int c = t / 96, k = t % 96;
        g_WihT[k*288 + c] = Wih[t];
        g_WhhT[k*288 + c] = Whh[t];
    }
    if (t < 96*192){
        int h = t / 192, k2 = t % 192;
        float v = Wa1[t];
        if (k2 < 96) g_WaiT[k2*96 + h] = v;
        else         g_WajT[(k2-96)*96 + h] = v;
    }
    if (t < 96*96){
        int h = t / 96, k = t % 96;
        g_Wo1T[k*96 + h] = Wo1[t];
        g_Wo2T[k*96 + h] = Wo2[t];
    }
}

// ---------------- init: x = leaky(x[:, :9] @ W_init.T + b_init) ------------
__global__ void k_init(const float* __restrict__ xin, const float* __restrict__ Wi,
                       const float* __restrict__ bi){
    int n = blockIdx.x, h = threadIdx.x;
    __shared__ float xr[9];
    if (h < 9) xr[h] = xin[n*10 + h];
    __syncthreads();
    float a = bi[h];
    #pragma unroll
    for (int k = 0; k < 9; k++) a = fmaf(xr[k], Wi[h*9 + k], a);
    g_bufA[n*H + h] = leaky(a);
}

// ---------------- m = x @ W_ggc ; zero s, cnt ------------------------------
__global__ void k_mm(int src, const float* __restrict__ Wg){
    const float* x = src ? g_bufB : g_bufA;
    int n = blockIdx.x, h = threadIdx.x;
    __shared__ float xr[H];
    xr[h] = x[n*H + h];
    __syncthreads();
    float a = 0.f;
    #pragma unroll 8
    for (int k = 0; k < H; k++) a = fmaf(xr[k], Wg[k*H + h], a);
    g_m[n*H + h] = a;
    g_s[n*H + h] = 0.f;
    if (h == 0) g_cnt[n] = 0.f;
}

// ---------------- segment sum over edges (validated indices only) ----------
__global__ void k_scatter(){
    int e = blockIdx.x;
    int s = g_src[e];
    int t = g_tgt[e];
    if (s < 0 || t < 0) return;
    int h = threadIdx.x;
    atomicAdd(&g_s[t*H + h], g_m[s*H + h]);
    if (h == 0) atomicAdd(&g_cnt[t], 1.0f);
}

// ---------------- GRU update + attention features hi / (hj+ba1) ------------
__global__ void k_gru(int src,
                      const float* __restrict__ bih, const float* __restrict__ bhh,
                      const float* __restrict__ ba1){
    float* x = src ? g_bufB : g_bufA;
    int n0 = blockIdx.x * NB;
    int h = threadIdx.x;
    __shared__ float ag[NB][H], xr[NB][H], xn[NB][H];
    #pragma unroll
    for (int r = 0; r < NB; r++){
        int n = n0 + r;
        float c = g_cnt[n];
        float inv = __fdividef(1.0f, fmaxf(c, 1.0f));
        ag[r][h] = g_s[n*H + h] * inv;
        xr[r][h] = x[n*H + h];
    }
    __syncthreads();
    float gir[NB], giz[NB], gin[NB], ghr[NB], ghz[NB], ghn[NB];
    #pragma unroll
    for (int r = 0; r < NB; r++){
        gir[r] = bih[h]; giz[r] = bih[h+H]; gin[r] = bih[h+2*H];
        ghr[r] = bhh[h]; ghz[r] = bhh[h+H]; ghn[r] = bhh[h+2*H];
    }
    for (int k = 0; k < H; k++){
        float wir = g_WihT[k*288 + h], wiz = g_WihT[k*288 + h + H], win = g_WihT[k*288 + h + 2*H];
        float whr = g_WhhT[k*288 + h], whz = g_WhhT[k*288 + h + H], whn = g_WhhT[k*288 + h + 2*H];
        #pragma unroll
        for (int r = 0; r < NB; r++){
            float a = ag[r][k], xv = xr[r][k];
            gir[r] = fmaf(a, wir, gir[r]); giz[r] = fmaf(a, wiz, giz[r]); gin[r] = fmaf(a, win, gin[r]);
            ghr[r] = fmaf(xv, whr, ghr[r]); ghz[r] = fmaf(xv, whz, ghz[r]); ghn[r] = fmaf(xv, whn, ghn[r]);
        }
    }
    #pragma unroll
    for (int r = 0; r < NB; r++){
        float rr = sigf(gir[r] + ghr[r]);
        float zz = sigf(giz[r] + ghz[r]);
        float nn = tanhf(gin[r] + rr * ghn[r]);
        float xv = (1.0f - zz) * nn + zz * xr[r][h];
        xn[r][h] = xv;
        x[(n0 + r)*H + h] = xv;
    }
    __syncthreads();
    float hiv[NB], hjv[NB];
    #pragma unroll
    for (int r = 0; r < NB; r++){ hiv[r] = 0.f; hjv[r] = ba1[h]; }
    for (int k = 0; k < H; k++){
        float wi = g_WaiT[k*H + h], wj = g_WajT[k*H + h];
        #pragma unroll
        for (int r = 0; r < NB; r++){
            float xk = xn[r][k];
            hiv[r] = fmaf(xk, wi, hiv[r]);
            hjv[r] = fmaf(xk, wj, hjv[r]);
        }
    }
    #pragma unroll
    for (int r = 0; r < NB; r++){
        g_hi[(n0 + r)*H + h] = hiv[r];
        g_hjb[(n0 + r)*H + h] = hjv[r];
    }
}

// ---------------- fused attention-coeff + sparse row matvec ---------------
// x_out[i,:] = sum_{j: adj[i,j]==1} sigma( sum_k sigma(hi[i,k]+hjb[j,k])*Wa2[k] + ba2 ) * x[j,:]
__global__ void k_pair(int src, const int* __restrict__ adj,
                       const float* __restrict__ Wa2, const float* __restrict__ ba2){
    const float* x   = src ? g_bufB : g_bufA;
    float* xout      = src ? g_bufA : g_bufB;
    int i = blockIdx.x;
    int w = threadIdx.x >> 5, lane = threadIdx.x & 31;
    float h0 = g_hi[i*H + lane], h1 = g_hi[i*H + 32 + lane], h2 = g_hi[i*H + 64 + lane];
    float w0 = Wa2[lane], w1 = Wa2[32 + lane], w2 = Wa2[64 + lane];
    float bb = ba2[0];
    float a0 = 0.f, a1 = 0.f, a2 = 0.f;
    const int* arow = adj + i*N;
    for (int j = w; j < N; j += PW){
        if (arow[j] == 1){
            const float* hj = g_hjb + j*H;
            float s =           sigf(h0 + hj[lane])      * w0;
            s = fmaf(sigf(h1 + hj[32 + lane]), w1, s);
            s = fmaf(sigf(h2 + hj[64 + lane]), w2, s);
            #pragma unroll
            for (int o = 16; o; o >>= 1) s += __shfl_xor_sync(0xffffffffu, s, o);
            float c = sigf(s + bb);
            const float* xj = x + j*H;
            a0 = fmaf(c, xj[lane],      a0);
            a1 = fmaf(c, xj[32 + lane], a1);
            a2 = fmaf(c, xj[64 + lane], a2);
        }
    }
    __shared__ float sacc[PW][H];
    sacc[w][lane]      = a0;
    sacc[w][32 + lane] = a1;
    sacc[w][64 + lane] = a2;
    __syncthreads();
    int t = threadIdx.x;
    if (t < H){
        float s = 0.f;
        #pragma unroll
        for (int r = 0; r < PW; r++) s += sacc[r][t];
        xout[i*H + t] = s;
    }
}

// ---------------- output head ---------------------------------------------
__global__ void k_out(int src,
                      const float* __restrict__ bo1, const float* __restrict__ bo2,
                      const float* __restrict__ Wp1, const float* __restrict__ bp1,
                      const float* __restrict__ Wp2, const float* __restrict__ bp2,
                      float* __restrict__ out){
    const float* x = src ? g_bufB : g_bufA;
    int n = blockIdx.x, h = threadIdx.x;
    __shared__ float x0[H], x1[H], r1[H], r2[H];
    x0[h] = x[n*H + h];
    __syncthreads();
    float a = bo1[h];
    for (int k = 0; k < H; k++) a = fmaf(x0[k], g_Wo1T[k*H + h], a);
    x1[h] = leaky(a);
    __syncthreads();
    float b = bo2[h];
    for (int k = 0; k < H; k++) b = fmaf(x1[k], g_Wo2T[k*H + h], b);
    float v = leaky(b);
    r1[h] = v * Wp1[h];
    r2[h] = v * Wp2[h];
    __syncthreads();
    if (h == 0){
        float s1 = 0.f, s2 = 0.f;
        for (int k = 0; k < H; k++){ s1 += r1[k]; s2 += r2[k]; }
        out[n]     = sigf(s1 + bp1[0]);
        out[N + n] = sigf(s2 + bp2[0]);
    }
}

// ---------------- launch ----------------------------------------------------
extern "C" void kernel_launch(void* const* d_in, const int* in_sizes, int n_in,
                              void* d_out, int out_size){
    const float* x_in  = (const float*)d_in[0];
    const int*   ei32  = (const int*)d_in[1];     // int32 or int64 storage — detected at runtime
    const int*   adj   = (const int*)d_in[2];
    const float* W_init= (const float*)d_in[3];
    const float* b_init= (const float*)d_in[4];
    const float* W_ggc = (const float*)d_in[5];
    const float* W_ih  = (const float*)d_in[6];
    const float* W_hh  = (const float*)d_in[7];
    const float* b_ih  = (const float*)d_in[8];
    const float* b_hh  = (const float*)d_in[9];
    const float* Wa1   = (const float*)d_in[10];
    const float* ba1   = (const float*)d_in[11];
    const float* Wa2   = (const float*)d_in[12];
    const float* ba2   = (const float*)d_in[13];
    const float* Wo1   = (const float*)d_in[14];
    const float* bo1   = (const float*)d_in[15];
    const float* Wo2   = (const float*)d_in[16];
    const float* bo2   = (const float*)d_in[17];
    const float* Wp1   = (const float*)d_in[18];
    const float* bp1   = (const float*)d_in[19];
    const float* Wp2   = (const float*)d_in[20];
    const float* bp2   = (const float*)d_in[21];
    float* out = (float*)d_out;

    k_decode<<<(E + 255)/256, 256>>>(ei32);
    k_prep<<<(288*96 + 255)/256, 256>>>(W_ih, W_hh, Wa1, Wo1, Wo2);
    k_init<<<N, H>>>(x_in, W_init, b_init);
    for (int u = 0; u < 2; u++){
        k_mm<<<N, H>>>(u, W_ggc);
        k_scatter<<<E, H>>>();
        k_gru<<<N/NB, H>>>(u, b_ih, b_hh, ba1);
        k_pair<<<N, 32*PW>>>(u, adj, Wa2, ba2);
    }
    // after u=0 data in bufB, after u=1 data in bufA
    k_out<<<N, H>>>(0, bo1, bo2, Wp1, bp1, Wp2, bp2, out);
}